// round 8
// baseline (speedup 1.0000x reference)
#include <cuda_runtime.h>
#include <cuda_bf16.h>

#define BB 16384
#define DD 256
constexpr int BD = BB * DD;
constexpr float GAMMA_ = 0.01f;
constexpr float HG = 0.005f;          // gamma/2
constexpr int SW = 132;               // smem row stride in 32-bit words (264 bf16)
constexpr int MT = 128;               // rows per CTA
constexpr int NTH = 512;              // 16 warps
constexpr int W_WORDS = DD * SW;      // 135168 B
constexpr int A_WORDS = MT * SW;      // 67584 B
constexpr size_t SME = (size_t)(W_WORDS + A_WORDS + DD) * 4;  // 203776 B

// ---------------- persistent state ----------------
__device__ float g_z[BD];
__device__ float g_v[BD];
__device__ float g_vh[BD];
__device__ float g_p[BD];
__device__ float g_q[BD];
__device__ float g_C[BD];

// ---------------- helpers ----------------
__device__ __forceinline__ void spsig(float x, float& sp, float& sg) {
    float ax = fabsf(x);
    float e = __expf(-ax);
    sp = fmaxf(x, 0.f) + __logf(1.f + e);
    sg = (x >= 0.f) ? __fdividef(1.f, 1.f + e) : __fdividef(e, 1.f + e);
}
__device__ __forceinline__ float softplus_f(float x) {
    return fmaxf(x, 0.f) + __logf(1.f + __expf(-fabsf(x)));
}

__device__ __forceinline__ void mma_16816(float* d, const unsigned* a, const unsigned* b) {
    asm volatile(
        "mma.sync.aligned.m16n8k16.row.col.f32.bf16.bf16.f32 "
        "{%0,%1,%2,%3}, {%4,%5,%6,%7}, {%8,%9}, {%0,%1,%2,%3};\n"
        : "+f"(d[0]), "+f"(d[1]), "+f"(d[2]), "+f"(d[3])
        : "r"(a[0]), "r"(a[1]), "r"(a[2]), "r"(a[3]), "r"(b[0]), "r"(b[1]));
}

__device__ __forceinline__ void ldsm_t4(unsigned& r0, unsigned& r1, unsigned& r2, unsigned& r3,
                                        unsigned addr) {
    asm volatile("ldmatrix.sync.aligned.m8n8.x4.trans.shared.b16 {%0,%1,%2,%3}, [%4];"
                 : "=r"(r0), "=r"(r1), "=r"(r2), "=r"(r3)
                 : "r"(addr));
}

// ---------------- fused epilogue element op ----------------
// Computes outputs for one adjacent column pair AND returns the bf16x2 word that
// becomes the NEXT phase's A-operand at this (row, col-pair).
// EPI 0: PQ     — p,q from a=acc+bias -> O0,O1; nextA = p*E0^2 - q        [E0 = v or vh]
// EPI 1: VSTEP  — vn = E0 - HG*acc -> O0;        nextA = E1*vn^2 - E2     [E0=prev vh, E1=p, E2=q]
// EPI 2: VLAST  — vn = E0 - HG*acc -> O0;        nextA = vn
// EPI 3: T      — t = 0.5*sg(a)/sp(a);           nextA = t               (no global write)
// EPI 4: CADD   — C = HG*(E0/E1)*E2 - g*acc ->O0; nextA = E3 (=z)
// EPI 5: ZSTEP  — zn = E0 + E1 + HG*sp(a)*E2 ->O0; nextA = zn            [E0=z,E1=C,E2=vh]
// EPI 6: VFINAL — vn = E0 - HG*acc -> O0;        nextA = E1 (=z)
template <int EPI>
__device__ __forceinline__ unsigned epi2(float a0, float a1, int off, int c,
                                         const float* __restrict__ sbias,
                                         const float* __restrict__ E0,
                                         const float* __restrict__ E1,
                                         const float* __restrict__ E2,
                                         const float* __restrict__ E3,
                                         float* __restrict__ O0, float* __restrict__ O1) {
    float2 x;
    if (EPI == 0) {
        a0 += sbias[c]; a1 += sbias[c + 1];
        float sp0, sg0, sp1, sg1;
        spsig(a0, sp0, sg0);
        spsig(a1, sp1, sg1);
        float p0 = 0.5f * sg0, p1 = 0.5f * sg1;
        float q0 = __fdividef(p0, sp0), q1 = __fdividef(p1, sp1);
        *(float2*)(O0 + off) = make_float2(p0, p1);
        *(float2*)(O1 + off) = make_float2(q0, q1);
        float2 vv = *(const float2*)(E0 + off);
        x = make_float2(p0 * vv.x * vv.x - q0, p1 * vv.y * vv.y - q1);
    } else if (EPI == 1 || EPI == 2) {
        float2 vk = *(const float2*)(E0 + off);
        float2 vn = make_float2(vk.x - HG * a0, vk.y - HG * a1);
        *(float2*)(O0 + off) = vn;
        if (EPI == 1) {
            float2 pp = *(const float2*)(E1 + off);
            float2 qq = *(const float2*)(E2 + off);
            x = make_float2(pp.x * vn.x * vn.x - qq.x, pp.y * vn.y * vn.y - qq.y);
        } else {
            x = vn;
        }
    } else if (EPI == 3) {
        a0 += sbias[c]; a1 += sbias[c + 1];
        float sp0, sg0, sp1, sg1;
        spsig(a0, sp0, sg0);
        spsig(a1, sp1, sg1);
        x = make_float2(__fdividef(0.5f * sg0, sp0), __fdividef(0.5f * sg1, sp1));
    } else if (EPI == 4) {
        float2 pp = *(const float2*)(E0 + off);
        float2 qq = *(const float2*)(E1 + off);
        float2 vv = *(const float2*)(E2 + off);
        float s0 = __fdividef(pp.x, qq.x), s1 = __fdividef(pp.y, qq.y);  // softplus(a_old)
        *(float2*)(O0 + off) = make_float2(HG * s0 * vv.x - GAMMA_ * a0,
                                           HG * s1 * vv.y - GAMMA_ * a1);
        x = *(const float2*)(E3 + off);
    } else if (EPI == 5) {
        a0 += sbias[c]; a1 += sbias[c + 1];
        float2 zz = *(const float2*)(E0 + off);
        float2 CC = *(const float2*)(E1 + off);
        float2 vv = *(const float2*)(E2 + off);
        float zn0 = zz.x + CC.x + HG * softplus_f(a0) * vv.x;
        float zn1 = zz.y + CC.y + HG * softplus_f(a1) * vv.y;
        *(float2*)(O0 + off) = make_float2(zn0, zn1);
        x = make_float2(zn0, zn1);
    } else {  // EPI == 6
        float2 vh = *(const float2*)(E0 + off);
        *(float2*)(O0 + off) = make_float2(vh.x - HG * a0, vh.y - HG * a1);
        x = *(const float2*)(E1 + off);
    }
    __nv_bfloat162 h = __float22bfloat162_rn(x);
    return *reinterpret_cast<unsigned*>(&h);
}

// ---------------- one phase: mainloop on shA -> fused epilogue writes next shA ----------------
//   BT=false: B[n][k] = W[n][k] (x @ W^T)  -> direct LDS
//   BT=true : B[n][k] = W[k][n] (x @ W)    -> ldmatrix.trans
template <int EPI, bool BT>
__device__ __forceinline__ void phase(
    const unsigned* __restrict__ shW, unsigned* __restrict__ shA,
    const float* __restrict__ sbias, unsigned wbase, int row0, int tid,
    const float* __restrict__ E0, const float* __restrict__ E1,
    const float* __restrict__ E2, const float* __restrict__ E3,
    float* __restrict__ O0, float* __restrict__ O1) {
    const int lane = tid & 31, warp = tid >> 5;
    const int wM = warp >> 2, wN = warp & 3;  // 4x4 warps: 32 rows x 64 cols
    const int g = lane >> 2, qd = lane & 3;
    const int sub = lane >> 3, rr = lane & 7;

    float acc[2][8][4];
#pragma unroll
    for (int mt = 0; mt < 2; ++mt)
#pragma unroll
        for (int nt = 0; nt < 8; ++nt)
#pragma unroll
            for (int i = 0; i < 4; ++i) acc[mt][nt][i] = 0.f;

#pragma unroll 1
    for (int kt = 0; kt < 16; ++kt) {
        const int kw = kt * 8 + qd;
        unsigned aF[2][4];
#pragma unroll
        for (int mt = 0; mt < 2; ++mt) {
            int r = wM * 32 + mt * 16 + g;
            aF[mt][0] = shA[r * SW + kw];
            aF[mt][1] = shA[(r + 8) * SW + kw];
            aF[mt][2] = shA[r * SW + kw + 4];
            aF[mt][3] = shA[(r + 8) * SW + kw + 4];
        }
        unsigned bF[8][2];
        if (!BT) {
#pragma unroll
            for (int nt = 0; nt < 8; ++nt) {
                int n = wN * 64 + nt * 8 + g;
                bF[nt][0] = shW[n * SW + kw];
                bF[nt][1] = shW[n * SW + kw + 4];
            }
        } else {
#pragma unroll
            for (int np = 0; np < 4; ++np) {
                int rowk = kt * 16 + (sub & 1) * 8 + rr;
                int coln = wN * 64 + np * 16 + (sub >> 1) * 8;
                unsigned a = wbase + (unsigned)(rowk * SW * 4 + coln * 2);
                ldsm_t4(bF[2 * np][0], bF[2 * np][1], bF[2 * np + 1][0], bF[2 * np + 1][1], a);
            }
        }
#pragma unroll
        for (int mt = 0; mt < 2; ++mt)
#pragma unroll
            for (int nt = 0; nt < 8; ++nt) mma_16816(acc[mt][nt], aF[mt], bF[nt]);
    }
    __syncthreads();  // all warps done reading shA before epilogue overwrites it

    // fused epilogue: global state updates + next A-tile into shA
#pragma unroll
    for (int mt = 0; mt < 2; ++mt) {
        int lr = wM * 32 + mt * 16 + g;
#pragma unroll
        for (int nt = 0; nt < 8; ++nt) {
            int c = wN * 64 + nt * 8 + qd * 2;
            int off0 = (row0 + lr) * DD + c;
            int off1 = (row0 + lr + 8) * DD + c;
            unsigned w0 = epi2<EPI>(acc[mt][nt][0], acc[mt][nt][1], off0, c,
                                    sbias, E0, E1, E2, E3, O0, O1);
            unsigned w1 = epi2<EPI>(acc[mt][nt][2], acc[mt][nt][3], off1, c,
                                    sbias, E0, E1, E2, E3, O0, O1);
            shA[lr * SW + (c >> 1)] = w0;
            shA[(lr + 8) * SW + (c >> 1)] = w1;
        }
    }
    __syncthreads();  // next A-tile + global writes visible CTA-wide
}

// ---------------- persistent kernel ----------------
__global__ __launch_bounds__(NTH, 1) void k_persist(
    const float* __restrict__ z0, const float* __restrict__ v0,
    const float* __restrict__ W, const float* __restrict__ bias,
    float* __restrict__ out) {
    extern __shared__ unsigned sh[];
    unsigned* shW = sh;                        // 256 x 132 words (bf16 W[i][j])
    unsigned* shA = sh + W_WORDS;              // 128 x 132 words
    float* sbias = (float*)(sh + W_WORDS + A_WORDS);
    const int tid = threadIdx.x;
    const int row0 = blockIdx.x * MT;
    const unsigned wbase = (unsigned)__cvta_generic_to_shared(shW);

    // load W (fp32 -> bf16) once
#pragma unroll 4
    for (int it = 0; it < 64; ++it) {
        int idx = it * NTH + tid;
        int i = idx >> 7, j2 = idx & 127;
        float2 wv = ((const float2*)W)[i * 128 + j2];
        __nv_bfloat162 h = __float22bfloat162_rn(wv);
        shW[i * SW + j2] = *reinterpret_cast<unsigned*>(&h);
    }
    if (tid < DD) sbias[tid] = bias[tid];

    // init state + first A-tile (= bf16(z0))
#pragma unroll 4
    for (int it = 0; it < 32; ++it) {
        int idx = it * NTH + tid;
        int row = idx >> 7, c2 = idx & 127;
        int go = (row0 + row) * (DD / 2) + c2;
        float2 xz = ((const float2*)z0)[go];
        float2 xv = ((const float2*)v0)[go];
        ((float2*)g_z)[go] = xz;
        ((float2*)g_v)[go] = xv;
        __nv_bfloat162 h = __float22bfloat162_rn(xz);
        shA[row * SW + c2] = *reinterpret_cast<unsigned*>(&h);
    }
    __syncthreads();

#pragma unroll 1
    for (int s = 0; s < 6; ++s) {
        // PQ1: a = z@W+bias -> p,q ; nextA = r(p,q,v)
        phase<0, true>(shW, shA, sbias, wbase, row0, tid,
                       g_v, nullptr, nullptr, nullptr, g_p, g_q);
        // VSTEP x7: vh_{k+1} = vh_k - HG*(r_k @ W^T); nextA = r_{k+1}
#pragma unroll 1
        for (int i = 0; i < 7; ++i) {
            const float* prev = i ? g_vh : g_v;
            phase<1, false>(shW, shA, sbias, wbase, row0, tid,
                            prev, g_p, g_q, nullptr, g_vh, nullptr);
        }
        // VLAST: final vh ; nextA = vh (feeds T)
        phase<2, false>(shW, shA, sbias, wbase, row0, tid,
                        g_vh, nullptr, nullptr, nullptr, g_vh, nullptr);
        // T: c = vh@W+bias -> t ; nextA = t (never hits global)
        phase<3, true>(shW, shA, sbias, wbase, row0, tid,
                       nullptr, nullptr, nullptr, nullptr, nullptr, nullptr);
        // CADD: C = HG*(p/q)*vh - GAMMA*(t @ W^T) ; nextA = z
        phase<4, false>(shW, shA, sbias, wbase, row0, tid,
                        g_p, g_q, g_vh, g_z, g_C, nullptr);
        // ZSTEP x8: z_{k+1} = z_k + C + HG*sp(z_k@W+bias)*vh ; nextA = z_{k+1}
#pragma unroll 1
        for (int i = 0; i < 8; ++i)
            phase<5, true>(shW, shA, sbias, wbase, row0, tid,
                           g_z, g_C, g_vh, nullptr, g_z, nullptr);
        // PQ2: p,q from z_new ; nextA = r(p,q,vh)
        phase<0, true>(shW, shA, sbias, wbase, row0, tid,
                       g_vh, nullptr, nullptr, nullptr, g_p, g_q);
        // VFINAL: v_new = vh - HG*(r @ W^T) ; nextA = z (feeds next step's PQ1)
        phase<6, false>(shW, shA, sbias, wbase, row0, tid,
                        g_vh, g_z, nullptr, nullptr, g_v, nullptr);
    }

    // output [z; v]
    {
        const int base = row0 * (DD / 4);
#pragma unroll
        for (int it = 0; it < 16; ++it) {
            int idx = base + it * NTH + tid;
            ((float4*)out)[idx] = ((const float4*)g_z)[idx];
            ((float4*)out)[BD / 4 + idx] = ((const float4*)g_v)[idx];
        }
    }
}

// ---------------- launch ----------------
extern "C" void kernel_launch(void* const* d_in, const int* in_sizes, int n_in,
                              void* d_out, int out_size) {
    const float* z0 = (const float*)d_in[0];
    const float* v0 = (const float*)d_in[1];
    const float* W = (const float*)d_in[2];
    const float* bias = (const float*)d_in[3];

    cudaFuncSetAttribute(k_persist, cudaFuncAttributeMaxDynamicSharedMemorySize, (int)SME);
    k_persist<<<BB / MT, NTH, SME>>>(z0, v0, W, bias, (float*)d_out);
}